// round 14
// baseline (speedup 1.0000x reference)
#include <cuda_runtime.h>
#include <cuda_fp16.h>
#include <math.h>
#include <stdint.h>

// ---------------------------------------------------------------------------
// FPLSTM: S=512, B=128, I=H=1024.
//   pre = X @ Wx^T + bx            (SIMT fp16 mma, cp.async 3-stage, 2 CTA/SM)
//   recurrence: 256 CTAs in 2 groups of 128, TWO co-resident CTAs per SM
//   (independent groups hide each other's stalls). CTA owns 8 h-columns;
//   fp16 weight slice (40 rows, 82.5KB) SMEM-resident; 2-stage cp.async
//   stream of the group's 64x1024 h/m tile; 8 segment launches of 64 steps.
// ---------------------------------------------------------------------------

namespace {
constexpr int SEQ  = 512;
constexpr int NB   = 128;
constexpr int K    = 1024;
constexpr int H    = 1024;
constexpr int NPRE = 5 * H;

constexpr int GCTA  = 128;           // CTAs per group
constexpr int GROWS = 64;            // batch rows per group
constexpr int UCOLS = 8;             // h-columns per CTA
constexpr int LDWW  = K / 2 + 4;     // 516 words
constexpr int BK    = 64;            // K-tile (halves)
constexpr int NKT   = K / BK;        // 16
constexpr int LDA   = 36;            // A row stride (words)
constexpr int ABUF  = GROWS * LDA;   // 2304 words / stage
constexpr int IOFP  = 9;             // padded col stride
constexpr int IOFSZ = GROWS * IOFP;  // 576 words

// lstm smem (words): total 27552 -> 110208 B  (2 CTAs/SM: 2x110208 < 227KB)
constexpr int OFF_W   = 0;                    // 40 rows x LDWW = 20640
constexpr int OFF_AS  = 40 * LDWW;            // 20640
constexpr int OFF_IOF = OFF_AS + 2 * ABUF;    // 25248
constexpr int OFF_C   = OFF_IOF + 3 * IOFSZ;  // 26976
constexpr int SMEM_WORDS = OFF_C + IOFSZ;     // 27552

constexpr int SEGS      = 8;
constexpr int SEG_STEPS = SEQ / SEGS;         // 64

constexpr int LDA_P  = 36;
constexpr int P_STAGE = 256 * LDA_P;
constexpr int P_SMEM  = 3 * P_STAGE;          // 110592 B
constexpr int BKP    = 64;
constexpr int NKT_P  = 16;
constexpr size_t X4 = (size_t)SEQ * NB * K / 4;
constexpr size_t W4 = (size_t)NPRE * K / 4;
}

__device__ __align__(16) float  g_pre[(size_t)SEQ * NB * NPRE];
__device__ __align__(16) __half g_xh[(size_t)SEQ * NB * K];
__device__ __align__(16) __half g_wxh[(size_t)NPRE * K];
__device__ __align__(16) __half g_hh[NB * H];
__device__ __align__(16) __half g_mh[NB * H];
__device__ __align__(16) float  g_c[NB * H];
__device__ unsigned g_bars[2];

__device__ __forceinline__ uint32_t pack_h2(float x, float y) {
    __half2 h = __floats2half2_rn(x, y);
    return *reinterpret_cast<uint32_t*>(&h);
}
__device__ __forceinline__ float fast_sigmoid(float x) {
    return __fdividef(1.0f, 1.0f + __expf(-x));
}
__device__ __forceinline__ float fast_tanh(float x) {
    return 1.0f - __fdividef(2.0f, __expf(2.0f * x) + 1.0f);
}
__device__ __forceinline__ void cp16(uint32_t saddr, const void* g) {
    asm volatile("cp.async.cg.shared.global [%0], [%1], 16;\n" :: "r"(saddr), "l"(g));
}
__device__ __forceinline__ void cp_commit() { asm volatile("cp.async.commit_group;\n"); }
template <int N> __device__ __forceinline__ void cp_wait() {
    asm volatile("cp.async.wait_group %0;\n" :: "n"(N));
}
__device__ __forceinline__ void mma_f16(float* c, const uint32_t* a, const uint32_t* b) {
    asm volatile(
        "mma.sync.aligned.m16n8k16.row.col.f32.f16.f16.f32 "
        "{%0,%1,%2,%3}, {%4,%5,%6,%7}, {%8,%9}, {%0,%1,%2,%3};\n"
        : "+f"(c[0]), "+f"(c[1]), "+f"(c[2]), "+f"(c[3])
        : "r"(a[0]), "r"(a[1]), "r"(a[2]), "r"(a[3]), "r"(b[0]), "r"(b[1]));
}

// ---------------------------------------------------------------------------
// round_kernel: fp16-convert X and Wx; zero c state; reset barriers
// ---------------------------------------------------------------------------
__global__ __launch_bounds__(256) void round_kernel(const float4* __restrict__ X,
                                                    const float4* __restrict__ Wx) {
    const size_t i = (size_t)blockIdx.x * 256 + threadIdx.x;
    if (i < 2) g_bars[i] = 0u;
    if (i < (size_t)(NB * H / 4))
        reinterpret_cast<float4*>(g_c)[i] = make_float4(0.f, 0.f, 0.f, 0.f);
    if (i < X4) {
        const float4 v = X[i];
        reinterpret_cast<uint2*>(g_xh)[i] = make_uint2(pack_h2(v.x, v.y), pack_h2(v.z, v.w));
    } else if (i < X4 + W4) {
        const size_t j = i - X4;
        const float4 v = Wx[j];
        reinterpret_cast<uint2*>(g_wxh)[j] = make_uint2(pack_h2(v.x, v.y), pack_h2(v.z, v.w));
    }
}

// ---------------------------------------------------------------------------
// pre_kernel: pre = Xh @ Wxh^T + bx  (2 CTA/SM, unchanged from R12)
// ---------------------------------------------------------------------------
__device__ __forceinline__ void pre_issue(uint32_t smbase, int stage,
                                          const __half* __restrict__ Asrc,
                                          const __half* __restrict__ Bsrc,
                                          int kt, int tid) {
    const uint32_t sb = smbase + (uint32_t)(stage * P_STAGE) * 4u;
    #pragma unroll
    for (int j = 0; j < 8; ++j) {
        const int i  = tid + j * 256;
        const int r  = i >> 3;
        const int ch = i & 7;
        const __half* src = (r < 128)
            ? Asrc + (size_t)r * K + kt + ch * 8
            : Bsrc + (size_t)(r - 128) * K + kt + ch * 8;
        cp16(sb + (uint32_t)(r * LDA_P + ch * 4) * 4u, src);
    }
    cp_commit();
}

__global__ __launch_bounds__(256, 2) void pre_kernel(const float* __restrict__ bx) {
    extern __shared__ uint32_t sm_u[];
    const uint32_t smbase = (uint32_t)__cvta_generic_to_shared(sm_u);
    const int tid  = threadIdx.x;
    const int lane = tid & 31;
    const int warp = tid >> 5;
    const int wm = warp >> 2;
    const int wn = warp & 3;
    const int ar = lane >> 2;
    const int aq = lane & 3;

    const __half* Asrc = g_xh  + (size_t)blockIdx.y * 128 * K;
    const __half* Bsrc = g_wxh + (size_t)blockIdx.x * 128 * K;
    float acc[4][4][4] = {};

    pre_issue(smbase, 0, Asrc, Bsrc, 0, tid);
    pre_issue(smbase, 1, Asrc, Bsrc, BKP, tid);

    #pragma unroll 1
    for (int kt = 0; kt < NKT_P; ++kt) {
        if (kt < NKT_P - 2) { cp_wait<1>(); } else { cp_wait<0>(); }
        __syncthreads();
        if (kt + 2 < NKT_P)
            pre_issue(smbase, (kt + 2) % 3, Asrc, Bsrc, (kt + 2) * BKP, tid);

        const uint32_t* buf = sm_u + (kt % 3) * P_STAGE;
        #pragma unroll
        for (int gq = 0; gq < 4; ++gq) {
            const int ac = gq * 8 + aq;
            uint32_t af[4][4], bf[4][2];
            #pragma unroll
            for (int tm = 0; tm < 4; ++tm) {
                const uint32_t* p = buf + (wm * 64 + tm * 16 + ar) * LDA_P + ac;
                af[tm][0] = p[0];
                af[tm][1] = p[8 * LDA_P];
                af[tm][2] = p[4];
                af[tm][3] = p[8 * LDA_P + 4];
            }
            #pragma unroll
            for (int tn = 0; tn < 4; ++tn) {
                const uint32_t* q = buf + (128 + wn * 32 + tn * 8 + ar) * LDA_P + ac;
                bf[tn][0] = q[0];
                bf[tn][1] = q[4];
            }
            #pragma unroll
            for (int tm = 0; tm < 4; ++tm)
                #pragma unroll
                for (int tn = 0; tn < 4; ++tn)
                    mma_f16(&acc[tm][tn][0], af[tm], bf[tn]);
        }
        __syncthreads();
    }

    #pragma unroll
    for (int tm = 0; tm < 4; ++tm)
        #pragma unroll
        for (int tn = 0; tn < 4; ++tn) {
            const int r0 = wm * 64 + tm * 16 + ar;
            const int c0 = wn * 32 + tn * 8 + aq * 2;
            #pragma unroll
            for (int j = 0; j < 4; ++j) {
                const int rr = r0 + (j >> 1) * 8;
                const int cc = c0 + (j & 1);
                const int gm = blockIdx.y * 128 + rr;
                const int gn = blockIdx.x * 128 + cc;
                g_pre[(size_t)gm * NPRE + gn] = acc[tm][tn][j] + __ldg(bx + gn);
            }
        }
}

// ---------------------------------------------------------------------------
// Persistent recurrence kernel: 256 CTAs, 2 per SM, 2 groups of 128
// ---------------------------------------------------------------------------
__device__ __forceinline__ void group_barrier(unsigned* bar, unsigned target) {
    __syncthreads();
    if (threadIdx.x == 0) {
        asm volatile("red.release.gpu.global.add.u32 [%0], %1;\n"
                     :: "l"(bar), "r"(1u) : "memory");
        unsigned v;
        do {
            asm volatile("ld.acquire.gpu.global.u32 %0, [%1];\n"
                         : "=r"(v) : "l"(bar) : "memory");
        } while (v < target);
    }
    __syncthreads();
}

// stage one 64 x 64-half A-tile (8KB), 2 cp16 per thread
__device__ __forceinline__ void lstm_issueA(uint32_t smbase, int stage,
                                            const __half* __restrict__ src,
                                            int kt, int tid) {
    const uint32_t sb = smbase + (uint32_t)(OFF_AS + stage * ABUF) * 4u;
    #pragma unroll
    for (int q = 0; q < 2; ++q) {
        const int i  = tid + q * 256;
        const int r  = i >> 3;
        const int ch = i & 7;
        cp16(sb + (uint32_t)(r * LDA + ch * 4) * 4u,
             src + (size_t)r * H + kt + ch * 8);
    }
    cp_commit();
}

__global__ __launch_bounds__(256, 2) void lstm_kernel(const float* __restrict__ Wh,
                                                      const float* __restrict__ bh,
                                                      const float* __restrict__ Wum,
                                                      const float* __restrict__ bum,
                                                      float* __restrict__ out,
                                                      int t0, unsigned tgt0) {
    extern __shared__ uint32_t sm_u[];
    const uint32_t smbase = (uint32_t)__cvta_generic_to_shared(sm_u);
    uint32_t* W_s = sm_u + OFF_W;
    float*    iof = reinterpret_cast<float*>(sm_u + OFF_IOF);
    float*    c_s = reinterpret_cast<float*>(sm_u + OFF_C);

    const int tid   = threadIdx.x;
    const int lane  = tid & 31;
    const int warp  = tid >> 5;
    const int cta   = blockIdx.x;
    const int grp   = cta >> 7;
    const int jj    = cta & 127;
    const int uBase = jj * UCOLS;
    const int gRow0 = grp * GROWS;
    unsigned* bar   = &g_bars[grp];

    // weights: rows r<32: Wh[((r>>3)*H + uBase + (r&7))*K]; rows 32..39: Wum
    for (int i = tid; i < 40 * 512; i += 256) {
        const int row = i >> 9;
        const int w   = i & 511;
        const float* src = (row < 32)
            ? Wh  + (size_t)((row >> 3) * H + uBase + (row & 7)) * K
            : Wum + (size_t)(uBase + (row - 32)) * K;
        const float2 v = *reinterpret_cast<const float2*>(src + w * 2);
        W_s[row * LDWW + w] = pack_h2(v.x, v.y);
    }
    // load c slice into smem (persisted across segments in g_c)
    for (int i = tid; i < GROWS * UCOLS; i += 256) {
        const int r = i >> 3;
        const int c = i & 7;
        c_s[r * IOFP + c] = g_c[(size_t)(gRow0 + r) * H + uBase + c];
    }
    __syncthreads();

    const int ar = lane >> 2;
    const int aq = lane & 3;
    const int wm = warp >> 1;          // 0..3 : 16 batch rows
    const int wn = warp & 1;           // 0..1 : gates {2wn, 2wn+1}

    float bhreg[2][2];                 // [tn][jb], gate = wn*2+tn
    #pragma unroll
    for (int tn = 0; tn < 2; ++tn)
        #pragma unroll
        for (int jb = 0; jb < 2; ++jb)
            bhreg[tn][jb] = bh[(wn * 2 + tn) * H + uBase + aq * 2 + jb];
    float bureg[2];
    bureg[0] = bum[uBase + aq * 2];
    bureg[1] = bum[uBase + aq * 2 + 1];

    unsigned tgt = tgt0;

    #pragma unroll 1
    for (int t = t0; t < t0 + SEG_STEPS; ++t) {
        const float* pre_t = g_pre + (size_t)t * NB * NPRE;

        // ================= Phase 1: 2 gates per warp for 16 rows x 8 cols ====
        {
            float acc[2][4] = {};
            if (t > 0) {
                const __half* hsrc = g_hh + (size_t)gRow0 * H;
                lstm_issueA(smbase, 0, hsrc, 0, tid);
                #pragma unroll 1
                for (int kt = 0; kt < NKT; ++kt) {
                    cp_wait<0>();
                    __syncthreads();
                    if (kt + 1 < NKT)
                        lstm_issueA(smbase, (kt + 1) & 1, hsrc, (kt + 1) * BK, tid);

                    const uint32_t* cur = sm_u + OFF_AS + (kt & 1) * ABUF;
                    #pragma unroll
                    for (int g4 = 0; g4 < 4; ++g4) {
                        const int ac = g4 * 8 + aq;
                        uint32_t af[4];
                        const uint32_t* p = cur + (wm * 16 + ar) * LDA + ac;
                        af[0] = p[0];
                        af[1] = p[8 * LDA];
                        af[2] = p[4];
                        af[3] = p[8 * LDA + 4];
                        #pragma unroll
                        for (int tn = 0; tn < 2; ++tn) {
                            uint32_t bf[2];
                            const uint32_t* q = W_s + (wn * 16 + tn * 8 + ar) * LDWW
                                              + kt * 32 + g4 * 8 + aq;
                            bf[0] = q[0];
                            bf[1] = q[4];
                            mma_f16(&acc[tn][0], af, bf);
                        }
                    }
                }
            }

            // epilogue (pre loaded here to cut mainloop register pressure)
            #pragma unroll
            for (int tn = 0; tn < 2; ++tn) {
                const int gate = wn * 2 + tn;
                #pragma unroll
                for (int jh = 0; jh < 2; ++jh) {
                    const int b = wm * 16 + ar + 8 * jh;
                    const float2 pv = __ldcg(reinterpret_cast<const float2*>(
                        pre_t + (size_t)(gRow0 + b) * NPRE + gate * H + uBase + aq * 2));
                    const float s0 = fast_sigmoid(acc[tn][2 * jh + 0] + bhreg[tn][0] + pv.x);
                    const float s1 = fast_sigmoid(acc[tn][2 * jh + 1] + bhreg[tn][1] + pv.y);
                    const int col0 = aq * 2;
                    if (gate == 2) {
                        const float m0 = s0 * fast_tanh(c_s[b * IOFP + col0]);
                        const float m1 = s1 * fast_tanh(c_s[b * IOFP + col0 + 1]);
                        *reinterpret_cast<uint32_t*>(
                            g_mh + (size_t)(gRow0 + b) * H + uBase + col0) = pack_h2(m0, m1);
                    } else {
                        const int slot = (gate == 3) ? 2 : gate;
                        iof[slot * IOFSZ + b * IOFP + col0]     = s0;
                        iof[slot * IOFSZ + b * IOFP + col0 + 1] = s1;
                    }
                }
            }
        }
        group_barrier(bar, tgt); tgt += GCTA;

        // ================= Phase 2: u + state update (warps 0-3 compute) =====
        {
            float acc2[4] = {};
            if (t > 0) {
                const __half* msrc = g_mh + (size_t)gRow0 * H;
                lstm_issueA(smbase, 0, msrc, 0, tid);
                #pragma unroll 1
                for (int kt = 0; kt < NKT; ++kt) {
                    cp_wait<0>();
                    __syncthreads();
                    if (kt + 1 < NKT)
                        lstm_issueA(smbase, (kt + 1) & 1, msrc, (kt + 1) * BK, tid);

                    if (warp < 4) {
                        const uint32_t* cur = sm_u + OFF_AS + (kt & 1) * ABUF;
                        #pragma unroll
                        for (int g4 = 0; g4 < 4; ++g4) {
                            const int ac = g4 * 8 + aq;
                            uint32_t af[4], bf[2];
                            const uint32_t* p = cur + (warp * 16 + ar) * LDA + ac;
                            af[0] = p[0];
                            af[1] = p[8 * LDA];
                            af[2] = p[4];
                            af[3] = p[8 * LDA + 4];
                            const uint32_t* q = W_s + (32 + ar) * LDWW
                                              + kt * 32 + g4 * 8 + aq;
                            bf[0] = q[0];
                            bf[1] = q[4];
                            mma_f16(acc2, af, bf);
                        }
                    }
                }
            }

            if (warp < 4) {
                const int col0 = aq * 2;
                #pragma unroll
                for (int jh = 0; jh < 2; ++jh) {
                    const int b = warp * 16 + ar + 8 * jh;
                    const float2 pv = __ldcg(reinterpret_cast<const float2*>(
                        pre_t + (size_t)(gRow0 + b) * NPRE + 4 * H + uBase + col0));
                    const float u0 = fast_tanh(acc2[2 * jh + 0] + bureg[0] + pv.x);
                    const float u1 = fast_tanh(acc2[2 * jh + 1] + bureg[1] + pv.y);
                    const float ig0 = iof[0 * IOFSZ + b * IOFP + col0];
                    const float ig1 = iof[0 * IOFSZ + b * IOFP + col0 + 1];
                    const float og0 = iof[1 * IOFSZ + b * IOFP + col0];
                    const float og1 = iof[1 * IOFSZ + b * IOFP + col0 + 1];
                    const float fg0 = iof[2 * IOFSZ + b * IOFP + col0];
                    const float fg1 = iof[2 * IOFSZ + b * IOFP + col0 + 1];
                    const float cn0 = ig0 * u0 + fg0 * c_s[b * IOFP + col0];
                    const float cn1 = ig1 * u1 + fg1 * c_s[b * IOFP + col0 + 1];
                    c_s[b * IOFP + col0]     = cn0;
                    c_s[b * IOFP + col0 + 1] = cn1;
                    const float hv0 = og0 * fast_tanh(cn0);
                    const float hv1 = og1 * fast_tanh(cn1);
                    *reinterpret_cast<float2*>(
                        out + ((size_t)t * NB + gRow0 + b) * H + uBase + col0) =
                        make_float2(hv0, hv1);
                    *reinterpret_cast<uint32_t*>(
                        g_hh + (size_t)(gRow0 + b) * H + uBase + col0) = pack_h2(hv0, hv1);
                    if (t == SEQ - 1) {
                        float* hn = out + ((size_t)SEQ * NB + gRow0 + b) * H + uBase + col0;
                        float* cn = hn + (size_t)NB * H;
                        *reinterpret_cast<float2*>(hn) = make_float2(hv0, hv1);
                        *reinterpret_cast<float2*>(cn) = make_float2(cn0, cn1);
                    }
                }
            }
        }
        group_barrier(bar, tgt); tgt += GCTA;
    }

    // persist c slice for next segment
    for (int i = tid; i < GROWS * UCOLS; i += 256) {
        const int r = i >> 3;
        const int c = i & 7;
        g_c[(size_t)(gRow0 + r) * H + uBase + c] = c_s[r * IOFP + c];
    }
}

extern "C" void kernel_launch(void* const* d_in, const int* in_sizes, int n_in,
                              void* d_out, int out_size) {
    (void)in_sizes; (void)n_in; (void)out_size;
    const float* X   = (const float*)d_in[0];
    const float* Wx  = (const float*)d_in[1];
    const float* bx  = (const float*)d_in[2];
    const float* Wh  = (const float*)d_in[3];
    const float* bh  = (const float*)d_in[4];
    const float* Wum = (const float*)d_in[5];
    const float* bum = (const float*)d_in[6];
    float* out = (float*)d_out;

    static_assert(SMEM_WORDS * 4 == 110208, "lstm smem layout");
    cudaFuncSetAttribute(lstm_kernel, cudaFuncAttributeMaxDynamicSharedMemorySize,
                         SMEM_WORDS * 4);
    cudaFuncSetAttribute(pre_kernel, cudaFuncAttributeMaxDynamicSharedMemorySize,
                         P_SMEM * 4);

    const size_t total4 = X4 + W4;
    round_kernel<<<(unsigned)((total4 + 255) / 256), 256>>>(
        (const float4*)X, (const float4*)Wx);
    pre_kernel<<<dim3(NPRE / 128, (SEQ * NB) / 128), 256, P_SMEM * 4>>>(bx);
    for (int s = 0; s < SEGS; ++s) {
        lstm_kernel<<<256, 256, SMEM_WORDS * 4>>>(
            Wh, bh, Wum, bum, out,
            s * SEG_STEPS, (unsigned)(s * SEG_STEPS * 2 * GCTA + GCTA));
    }
}

// round 15
// speedup vs baseline: 1.1023x; 1.1023x over previous
#include <cuda_runtime.h>
#include <cuda_fp16.h>
#include <math.h>
#include <stdint.h>

// ---------------------------------------------------------------------------
// FPLSTM: S=512, B=128, I=H=1024.
//   pre = X @ Wx^T + bx            (SIMT fp16 mma, cp.async 3-stage, 2 CTA/SM)
//   recurrence: 256 CTAs in 2 groups of 128, two co-resident CTAs per SM
//   (wave pairing (b, b+148) puts one CTA of each group on an SM; the groups
//   run independent barriers so they hide each other's stalls).
//   CTA owns 8 h-columns; fp16 weight slice (82.5KB) SMEM-resident;
//   2-stage / 1-tile-ahead cp.async stream of the group's 64x1024 h/m tile.
// ---------------------------------------------------------------------------

namespace {
constexpr int SEQ  = 512;
constexpr int NB   = 128;
constexpr int K    = 1024;
constexpr int H    = 1024;
constexpr int NPRE = 5 * H;

constexpr int GCTA  = 128;           // CTAs per group
constexpr int GROWS = 64;            // batch rows per group
constexpr int UCOLS = 8;             // h-columns per CTA
constexpr int LDWW  = K / 2 + 4;     // 516 words
constexpr int BK    = 64;            // K-tile (halves)
constexpr int NKT   = K / BK;        // 16
constexpr int LDA   = 36;            // A row stride (words)
constexpr int ABUF  = GROWS * LDA;   // 2304 words / stage
constexpr int IOFP  = 9;             // padded col stride
constexpr int IOFSZ = GROWS * IOFP;  // 576 words

// lstm smem (words): 27552 -> 110208 B (2 CTAs/SM fit: 220416 < 228KB)
constexpr int OFF_W   = 0;                    // 40 rows x LDWW = 20640
constexpr int OFF_AS  = 40 * LDWW;            // 20640
constexpr int OFF_IOF = OFF_AS + 2 * ABUF;    // 25248
constexpr int OFF_C   = OFF_IOF + 3 * IOFSZ;  // 26976
constexpr int SMEM_WORDS = OFF_C + IOFSZ;     // 27552

constexpr int SEGS      = 8;
constexpr int SEG_STEPS = SEQ / SEGS;         // 64

constexpr int LDA_P  = 36;
constexpr int P_STAGE = 256 * LDA_P;
constexpr int P_SMEM  = 3 * P_STAGE;          // 110592 B
constexpr int BKP    = 64;
constexpr int NKT_P  = 16;
constexpr size_t X4 = (size_t)SEQ * NB * K / 4;
constexpr size_t W4 = (size_t)NPRE * K / 4;
}

__device__ __align__(16) float  g_pre[(size_t)SEQ * NB * NPRE];
__device__ __align__(16) __half g_xh[(size_t)SEQ * NB * K];
__device__ __align__(16) __half g_wxh[(size_t)NPRE * K];
__device__ __align__(16) __half g_hh[NB * H];
__device__ __align__(16) __half g_mh[NB * H];
__device__ __align__(16) float  g_c[NB * H];
__device__ unsigned g_bars[2];

__device__ __forceinline__ uint32_t pack_h2(float x, float y) {
    __half2 h = __floats2half2_rn(x, y);
    return *reinterpret_cast<uint32_t*>(&h);
}
__device__ __forceinline__ float fast_sigmoid(float x) {
    return __fdividef(1.0f, 1.0f + __expf(-x));
}
__device__ __forceinline__ float fast_tanh(float x) {
    return 1.0f - __fdividef(2.0f, __expf(2.0f * x) + 1.0f);
}
__device__ __forceinline__ void cp16(uint32_t saddr, const void* g) {
    asm volatile("cp.async.cg.shared.global [%0], [%1], 16;\n" :: "r"(saddr), "l"(g));
}
__device__ __forceinline__ void cp_commit() { asm volatile("cp.async.commit_group;\n"); }
template <int N> __device__ __forceinline__ void cp_wait() {
    asm volatile("cp.async.wait_group %0;\n" :: "n"(N));
}
__device__ __forceinline__ void mma_f16(float* c, const uint32_t* a, const uint32_t* b) {
    asm volatile(
        "mma.sync.aligned.m16n8k16.row.col.f32.f16.f16.f32 "
        "{%0,%1,%2,%3}, {%4,%5,%6,%7}, {%8,%9}, {%0,%1,%2,%3};\n"
        : "+f"(c[0]), "+f"(c[1]), "+f"(c[2]), "+f"(c[3])
        : "r"(a[0]), "r"(a[1]), "r"(a[2]), "r"(a[3]), "r"(b[0]), "r"(b[1]));
}

// ---------------------------------------------------------------------------
// round_kernel: fp16-convert X and Wx; zero c state; reset barriers
// ---------------------------------------------------------------------------
__global__ __launch_bounds__(256) void round_kernel(const float4* __restrict__ X,
                                                    const float4* __restrict__ Wx) {
    const size_t i = (size_t)blockIdx.x * 256 + threadIdx.x;
    if (i < 2) g_bars[i] = 0u;
    if (i < (size_t)(NB * H / 4))
        reinterpret_cast<float4*>(g_c)[i] = make_float4(0.f, 0.f, 0.f, 0.f);
    if (i < X4) {
        const float4 v = X[i];
        reinterpret_cast<uint2*>(g_xh)[i] = make_uint2(pack_h2(v.x, v.y), pack_h2(v.z, v.w));
    } else if (i < X4 + W4) {
        const size_t j = i - X4;
        const float4 v = Wx[j];
        reinterpret_cast<uint2*>(g_wxh)[j] = make_uint2(pack_h2(v.x, v.y), pack_h2(v.z, v.w));
    }
}

// ---------------------------------------------------------------------------
// pre_kernel: pre = Xh @ Wxh^T + bx  (2 CTA/SM, unchanged from R12)
// ---------------------------------------------------------------------------
__device__ __forceinline__ void pre_issue(uint32_t smbase, int stage,
                                          const __half* __restrict__ Asrc,
                                          const __half* __restrict__ Bsrc,
                                          int kt, int tid) {
    const uint32_t sb = smbase + (uint32_t)(stage * P_STAGE) * 4u;
    #pragma unroll
    for (int j = 0; j < 8; ++j) {
        const int i  = tid + j * 256;
        const int r  = i >> 3;
        const int ch = i & 7;
        const __half* src = (r < 128)
            ? Asrc + (size_t)r * K + kt + ch * 8
            : Bsrc + (size_t)(r - 128) * K + kt + ch * 8;
        cp16(sb + (uint32_t)(r * LDA_P + ch * 4) * 4u, src);
    }
    cp_commit();
}

__global__ __launch_bounds__(256, 2) void pre_kernel(const float* __restrict__ bx) {
    extern __shared__ uint32_t sm_u[];
    const uint32_t smbase = (uint32_t)__cvta_generic_to_shared(sm_u);
    const int tid  = threadIdx.x;
    const int lane = tid & 31;
    const int warp = tid >> 5;
    const int wm = warp >> 2;
    const int wn = warp & 3;
    const int ar = lane >> 2;
    const int aq = lane & 3;

    const __half* Asrc = g_xh  + (size_t)blockIdx.y * 128 * K;
    const __half* Bsrc = g_wxh + (size_t)blockIdx.x * 128 * K;
    float acc[4][4][4] = {};

    pre_issue(smbase, 0, Asrc, Bsrc, 0, tid);
    pre_issue(smbase, 1, Asrc, Bsrc, BKP, tid);

    #pragma unroll 1
    for (int kt = 0; kt < NKT_P; ++kt) {
        if (kt < NKT_P - 2) { cp_wait<1>(); } else { cp_wait<0>(); }
        __syncthreads();
        if (kt + 2 < NKT_P)
            pre_issue(smbase, (kt + 2) % 3, Asrc, Bsrc, (kt + 2) * BKP, tid);

        const uint32_t* buf = sm_u + (kt % 3) * P_STAGE;
        #pragma unroll
        for (int gq = 0; gq < 4; ++gq) {
            const int ac = gq * 8 + aq;
            uint32_t af[4][4], bf[4][2];
            #pragma unroll
            for (int tm = 0; tm < 4; ++tm) {
                const uint32_t* p = buf + (wm * 64 + tm * 16 + ar) * LDA_P + ac;
                af[tm][0] = p[0];
                af[tm][1] = p[8 * LDA_P];
                af[tm][2] = p[4];
                af[tm][3] = p[8 * LDA_P + 4];
            }
            #pragma unroll
            for (int tn = 0; tn < 4; ++tn) {
                const uint32_t* q = buf + (128 + wn * 32 + tn * 8 + ar) * LDA_P + ac;
                bf[tn][0] = q[0];
                bf[tn][1] = q[4];
            }
            #pragma unroll
            for (int tm = 0; tm < 4; ++tm)
                #pragma unroll
                for (int tn = 0; tn < 4; ++tn)
                    mma_f16(&acc[tm][tn][0], af[tm], bf[tn]);
        }
        __syncthreads();
    }

    #pragma unroll
    for (int tm = 0; tm < 4; ++tm)
        #pragma unroll
        for (int tn = 0; tn < 4; ++tn) {
            const int r0 = wm * 64 + tm * 16 + ar;
            const int c0 = wn * 32 + tn * 8 + aq * 2;
            #pragma unroll
            for (int j = 0; j < 4; ++j) {
                const int rr = r0 + (j >> 1) * 8;
                const int cc = c0 + (j & 1);
                const int gm = blockIdx.y * 128 + rr;
                const int gn = blockIdx.x * 128 + cc;
                g_pre[(size_t)gm * NPRE + gn] = acc[tm][tn][j] + __ldg(bx + gn);
            }
        }
}

// ---------------------------------------------------------------------------
// Persistent recurrence kernel: 256 CTAs, 2 per SM (cross-group pairs)
// ---------------------------------------------------------------------------
__device__ __forceinline__ void group_barrier(unsigned* bar, unsigned target) {
    __syncthreads();
    if (threadIdx.x == 0) {
        asm volatile("red.release.gpu.global.add.u32 [%0], %1;\n"
                     :: "l"(bar), "r"(1u) : "memory");
        unsigned v;
        do {
            asm volatile("ld.acquire.gpu.global.u32 %0, [%1];\n"
                         : "=r"(v) : "l"(bar) : "memory");
        } while (v < target);
    }
    __syncthreads();
}

// stage one 64 x 64-half A-tile (8KB), 2 cp16 per thread
__device__ __forceinline__ void lstm_issueA(uint32_t smbase, int stage,
                                            const __half* __restrict__ src,
                                            int kt, int tid) {
    const uint32_t sb = smbase + (uint32_t)(OFF_AS + stage * ABUF) * 4u;
    #pragma unroll
    for (int q = 0; q < 2; ++q) {
        const int i  = tid + q * 256;
        const int r  = i >> 3;
        const int ch = i & 7;
        cp16(sb + (uint32_t)(r * LDA + ch * 4) * 4u,
             src + (size_t)r * H + kt + ch * 8);
    }
    cp_commit();
}

__global__ __launch_bounds__(256, 2) void lstm_kernel(const float* __restrict__ Wh,
                                                      const float* __restrict__ bh,
                                                      const float* __restrict__ Wum,
                                                      const float* __restrict__ bum,
                                                      float* __restrict__ out,
                                                      int t0, unsigned tgt0) {
    extern __shared__ uint32_t sm_u[];
    const uint32_t smbase = (uint32_t)__cvta_generic_to_shared(sm_u);
    uint32_t* W_s = sm_u + OFF_W;
    float*    iof = reinterpret_cast<float*>(sm_u + OFF_IOF);
    float*    c_s = reinterpret_cast<float*>(sm_u + OFF_C);

    const int tid   = threadIdx.x;
    const int lane  = tid & 31;
    const int warp  = tid >> 5;
    const int cta   = blockIdx.x;
    const int grp   = cta >> 7;      // wave pairing (b, b+148) => cross-group
    const int jj    = cta & 127;
    const int uBase = jj * UCOLS;
    const int gRow0 = grp * GROWS;
    unsigned* bar   = &g_bars[grp];

    // weights: rows r<32: Wh[((r>>3)*H + uBase + (r&7))*K]; rows 32..39: Wum
    for (int i = tid; i < 40 * 512; i += 256) {
        const int row = i >> 9;
        const int w   = i & 511;
        const float* src = (row < 32)
            ? Wh  + (size_t)((row >> 3) * H + uBase + (row & 7)) * K
            : Wum + (size_t)(uBase + (row - 32)) * K;
        const float2 v = *reinterpret_cast<const float2*>(src + w * 2);
        W_s[row * LDWW + w] = pack_h2(v.x, v.y);
    }
    for (int i = tid; i < GROWS * UCOLS; i += 256) {
        const int r = i >> 3;
        const int c = i & 7;
        c_s[r * IOFP + c] = g_c[(size_t)(gRow0 + r) * H + uBase + c];
    }
    __syncthreads();

    const int ar = lane >> 2;
    const int aq = lane & 3;
    const int wm = warp >> 1;          // 0..3 : 16 batch rows
    const int wn = warp & 1;           // 0..1 : gates {2wn, 2wn+1}

    float bhreg[2][2];
    #pragma unroll
    for (int tn = 0; tn < 2; ++tn)
        #pragma unroll
        for (int jb = 0; jb < 2; ++jb)
            bhreg[tn][jb] = bh[(wn * 2 + tn) * H + uBase + aq * 2 + jb];
    float bureg[2];
    bureg[0] = bum[uBase + aq * 2];
    bureg[1] = bum[uBase + aq * 2 + 1];

    unsigned tgt = tgt0;

    #pragma unroll 1
    for (int t = t0; t < t0 + SEG_STEPS; ++t) {
        const float* pre_t = g_pre + (size_t)t * NB * NPRE;

        // ================= Phase 1: 2 gates per warp for 16 rows x 8 cols ====
        {
            float acc[2][4] = {};
            if (t > 0) {
                const __half* hsrc = g_hh + (size_t)gRow0 * H;
                lstm_issueA(smbase, 0, hsrc, 0, tid);
                lstm_issueA(smbase, 1, hsrc, BK, tid);
                #pragma unroll 1
                for (int kt = 0; kt < NKT; ++kt) {
                    if (kt < NKT - 1) { cp_wait<1>(); } else { cp_wait<0>(); }
                    __syncthreads();

                    const uint32_t* cur = sm_u + OFF_AS + (kt & 1) * ABUF;
                    #pragma unroll
                    for (int g4 = 0; g4 < 4; ++g4) {
                        const int ac = g4 * 8 + aq;
                        uint32_t af[4];
                        const uint32_t* p = cur + (wm * 16 + ar) * LDA + ac;
                        af[0] = p[0];
                        af[1] = p[8 * LDA];
                        af[2] = p[4];
                        af[3] = p[8 * LDA + 4];
                        #pragma unroll
                        for (int tn = 0; tn < 2; ++tn) {
                            uint32_t bf[2];
                            const uint32_t* q = W_s + (wn * 16 + tn * 8 + ar) * LDWW
                                              + kt * 32 + g4 * 8 + aq;
                            bf[0] = q[0];
                            bf[1] = q[4];
                            mma_f16(&acc[tn][0], af, bf);
                        }
                    }
                    __syncthreads();
                    if (kt + 2 < NKT)
                        lstm_issueA(smbase, kt & 1, hsrc, (kt + 2) * BK, tid);
                }
            }

            // epilogue
            #pragma unroll
            for (int tn = 0; tn < 2; ++tn) {
                const int gate = wn * 2 + tn;
                #pragma unroll
                for (int jh = 0; jh < 2; ++jh) {
                    const int b = wm * 16 + ar + 8 * jh;
                    const float2 pv = __ldcg(reinterpret_cast<const float2*>(
                        pre_t + (size_t)(gRow0 + b) * NPRE + gate * H + uBase + aq * 2));
                    const float s0 = fast_sigmoid(acc[tn][2 * jh + 0] + bhreg[tn][0] + pv.x);
                    const float s1 = fast_sigmoid(acc[tn][2 * jh + 1] + bhreg[tn][1] + pv.y);
                    const int col0 = aq * 2;
                    if (gate == 2) {
                        const float m0 = s0 * fast_tanh(c_s[b * IOFP + col0]);
                        const float m1 = s1 * fast_tanh(c_s[b * IOFP + col0 + 1]);
                        *reinterpret_cast<uint32_t*>(
                            g_mh + (size_t)(gRow0 + b) * H + uBase + col0) = pack_h2(m0, m1);
                    } else {
                        const int slot = (gate == 3) ? 2 : gate;
                        iof[slot * IOFSZ + b * IOFP + col0]     = s0;
                        iof[slot * IOFSZ + b * IOFP + col0 + 1] = s1;
                    }
                }
            }
        }
        group_barrier(bar, tgt); tgt += GCTA;

        // ================= Phase 2: u + state update (warps 0-3 compute) =====
        {
            float acc2[4] = {};
            if (t > 0) {
                const __half* msrc = g_mh + (size_t)gRow0 * H;
                lstm_issueA(smbase, 0, msrc, 0, tid);
                lstm_issueA(smbase, 1, msrc, BK, tid);
                #pragma unroll 1
                for (int kt = 0; kt < NKT; ++kt) {
                    if (kt < NKT - 1) { cp_wait<1>(); } else { cp_wait<0>(); }
                    __syncthreads();

                    if (warp < 4) {
                        const uint32_t* cur = sm_u + OFF_AS + (kt & 1) * ABUF;
                        #pragma unroll
                        for (int g4 = 0; g4 < 4; ++g4) {
                            const int ac = g4 * 8 + aq;
                            uint32_t af[4], bf[2];
                            const uint32_t* p = cur + (warp * 16 + ar) * LDA + ac;
                            af[0] = p[0];
                            af[1] = p[8 * LDA];
                            af[2] = p[4];
                            af[3] = p[8 * LDA + 4];
                            const uint32_t* q = W_s + (32 + ar) * LDWW
                                              + kt * 32 + g4 * 8 + aq;
                            bf[0] = q[0];
                            bf[1] = q[4];
                            mma_f16(acc2, af, bf);
                        }
                    }
                    __syncthreads();
                    if (kt + 2 < NKT)
                        lstm_issueA(smbase, kt & 1, msrc, (kt + 2) * BK, tid);
                }
            }

            if (warp < 4) {
                const int col0 = aq * 2;
                #pragma unroll
                for (int jh = 0; jh < 2; ++jh) {
                    const int b = warp * 16 + ar + 8 * jh;
                    const float2 pv = __ldcg(reinterpret_cast<const float2*>(
                        pre_t + (size_t)(gRow0 + b) * NPRE + 4 * H + uBase + col0));
                    const float u0 = fast_tanh(acc2[2 * jh + 0] + bureg[0] + pv.x);
                    const float u1 = fast_tanh(acc2[2 * jh + 1] + bureg[1] + pv.y);
                    const float ig0 = iof[0 * IOFSZ + b * IOFP + col0];
                    const float ig1 = iof[0 * IOFSZ + b * IOFP + col0 + 1];
                    const float og0 = iof[1 * IOFSZ + b * IOFP + col0];
                    const float og1 = iof[1 * IOFSZ + b * IOFP + col0 + 1];
                    const float fg0 = iof[2 * IOFSZ + b * IOFP + col0];
                    const float fg1 = iof[2 * IOFSZ + b * IOFP + col0 + 1];
                    const float cn0 = ig0 * u0 + fg0 * c_s[b * IOFP + col0];
                    const float cn1 = ig1 * u1 + fg1 * c_s[b * IOFP + col0 + 1];
                    c_s[b * IOFP + col0]     = cn0;
                    c_s[b * IOFP + col0 + 1] = cn1;
                    const float hv0 = og0 * fast_tanh(cn0);
                    const float hv1 = og1 * fast_tanh(cn1);
                    *reinterpret_cast<float2*>(
                        out + ((size_t)t * NB + gRow0 + b) * H + uBase + col0) =
                        make_float2(hv0, hv1);
                    *reinterpret_cast<uint32_t*>(
                        g_hh + (size_t)(gRow0 + b) * H + uBase + col0) = pack_h2(hv0, hv1);
                    if (t == SEQ - 1) {
                        float* hn = out + ((size_t)SEQ * NB + gRow0 + b) * H + uBase + col0;
                        float* cn = hn + (size_t)NB * H;
                        *reinterpret_cast<float2*>(hn) = make_float2(hv0, hv1);
                        *reinterpret_cast<float2*>(cn) = make_float2(cn0, cn1);
                    }
                }
            }
        }
        group_barrier(bar, tgt); tgt += GCTA;
    }

    // persist c slice for next segment
    for (int i = tid; i < GROWS * UCOLS; i += 256) {
        const int r = i >> 3;
        const int c = i & 7;
        g_c[(size_t)(gRow0 + r) * H + uBase + c] = c_s[r * IOFP + c];
    }
}

extern "C" void kernel_launch(void* const* d_in, const int* in_sizes, int n_in,
                              void* d_out, int out_size) {
    (void)in_sizes; (void)n_in; (void)out_size;
    const float* X   = (const float*)d_in[0];
    const float* Wx  = (const float*)d_in[1];
    const float* bx  = (const float*)d_in[2];
    const float* Wh  = (const float*)d_in[3];
    const float* bh  = (const float*)d_in[4];
    const float* Wum = (const float*)d_in[5];
    const float* bum = (const float*)d_in[6];
    float* out = (float*)d_out;

    static_assert(SMEM_WORDS * 4 == 110208, "lstm smem layout");
    cudaFuncSetAttribute(lstm_kernel, cudaFuncAttributeMaxDynamicSharedMemorySize,
                         SMEM_WORDS * 4);
    cudaFuncSetAttribute(pre_kernel, cudaFuncAttributeMaxDynamicSharedMemorySize,
                         P_SMEM * 4);

    const size_t total4 = X4 + W4;
    round_kernel<<<(unsigned)((total4 + 255) / 256), 256>>>(
        (const float4*)X, (const float4*)Wx);
    pre_kernel<<<dim3(NPRE / 128, (SEQ * NB) / 128), 256, P_SMEM * 4>>>(bx);
    for (int s = 0; s < SEGS; ++s) {
        lstm_kernel<<<256, 256, SMEM_WORDS * 4>>>(
            Wh, bh, Wum, bum, out,
            s * SEG_STEPS, (unsigned)(s * SEG_STEPS * 2 * GCTA + GCTA));
    }
}

// round 16
// speedup vs baseline: 1.3859x; 1.2572x over previous
#include <cuda_runtime.h>
#include <cuda_fp16.h>
#include <math.h>
#include <stdint.h>

// ---------------------------------------------------------------------------
// FPLSTM: S=512, B=128, I=H=1024.
//   pre = X @ Wx^T + bx            (SIMT fp16 mma, cp.async 3-stage, 2 CTA/SM)
//   recurrence: persistent CTAs, 2 independent groups of 64, 2 segment
//   launches of 256 steps; each warp owns (16 rows x 8 cols), computes all
//   4 gates AND u for those cells -> i/o/f/c in registers, no smem state.
//   6-stage / 5-ahead cp.async pipeline on the streamed h/m tiles.
//   (= round-12 best configuration with segmentation overhead stripped)
// ---------------------------------------------------------------------------

namespace {
constexpr int SEQ  = 512;
constexpr int NB   = 128;
constexpr int K    = 1024;
constexpr int H    = 1024;
constexpr int NPRE = 5 * H;

constexpr int GCTA  = 64;
constexpr int GROWS = 64;
constexpr int UCOLS = 16;
constexpr int LDWW  = K / 2 + 4;     // 516 words
constexpr int BK    = 64;
constexpr int NKT   = K / BK;        // 16
constexpr int LDA   = 36;
constexpr int ABUF  = GROWS * LDA;   // 2304 words (9216 B) per stage
constexpr int NSTG  = 6;

constexpr int OFF_W   = 0;                       // 80 rows x LDWW
constexpr int OFF_AS  = 80 * LDWW;               // 41280
constexpr int SMEM_WORDS = OFF_AS + NSTG * ABUF; // 55104 -> 220416 B

constexpr int SEGS      = 2;
constexpr int SEG_STEPS = SEQ / SEGS;            // 256

constexpr int LDA_P  = 36;
constexpr int P_STAGE = 256 * LDA_P;
constexpr int P_SMEM  = 3 * P_STAGE;             // 110592 B
constexpr int BKP    = 64;
constexpr int NKT_P  = 16;
constexpr size_t X4 = (size_t)SEQ * NB * K / 4;
constexpr size_t W4 = (size_t)NPRE * K / 4;
}

__device__ __align__(16) float  g_pre[(size_t)SEQ * NB * NPRE];
__device__ __align__(16) __half g_xh[(size_t)SEQ * NB * K];
__device__ __align__(16) __half g_wxh[(size_t)NPRE * K];
__device__ __align__(16) __half g_hh[NB * H];
__device__ __align__(16) __half g_mh[NB * H];
__device__ __align__(16) float  g_c[NB * H];
__device__ unsigned g_bars[2];

__device__ __forceinline__ uint32_t pack_h2(float x, float y) {
    __half2 h = __floats2half2_rn(x, y);
    return *reinterpret_cast<uint32_t*>(&h);
}
__device__ __forceinline__ float fast_sigmoid(float x) {
    return __fdividef(1.0f, 1.0f + __expf(-x));
}
__device__ __forceinline__ float fast_tanh(float x) {
    return 1.0f - __fdividef(2.0f, __expf(2.0f * x) + 1.0f);
}
__device__ __forceinline__ void cp16(uint32_t saddr, const void* g) {
    asm volatile("cp.async.cg.shared.global [%0], [%1], 16;\n" :: "r"(saddr), "l"(g));
}
__device__ __forceinline__ void cp_commit() { asm volatile("cp.async.commit_group;\n"); }
template <int N> __device__ __forceinline__ void cp_wait() {
    asm volatile("cp.async.wait_group %0;\n" :: "n"(N));
}
__device__ __forceinline__ void mma_f16(float* c, const uint32_t* a, const uint32_t* b) {
    asm volatile(
        "mma.sync.aligned.m16n8k16.row.col.f32.f16.f16.f32 "
        "{%0,%1,%2,%3}, {%4,%5,%6,%7}, {%8,%9}, {%0,%1,%2,%3};\n"
        : "+f"(c[0]), "+f"(c[1]), "+f"(c[2]), "+f"(c[3])
        : "r"(a[0]), "r"(a[1]), "r"(a[2]), "r"(a[3]), "r"(b[0]), "r"(b[1]));
}

// ---------------------------------------------------------------------------
// round_kernel: fp16-convert X and Wx; zero c state; reset barriers
// ---------------------------------------------------------------------------
__global__ __launch_bounds__(256) void round_kernel(const float4* __restrict__ X,
                                                    const float4* __restrict__ Wx) {
    const size_t i = (size_t)blockIdx.x * 256 + threadIdx.x;
    if (i < 2) g_bars[i] = 0u;
    if (i < (size_t)(NB * H / 4))
        reinterpret_cast<float4*>(g_c)[i] = make_float4(0.f, 0.f, 0.f, 0.f);
    if (i < X4) {
        const float4 v = X[i];
        reinterpret_cast<uint2*>(g_xh)[i] = make_uint2(pack_h2(v.x, v.y), pack_h2(v.z, v.w));
    } else if (i < X4 + W4) {
        const size_t j = i - X4;
        const float4 v = Wx[j];
        reinterpret_cast<uint2*>(g_wxh)[j] = make_uint2(pack_h2(v.x, v.y), pack_h2(v.z, v.w));
    }
}

// ---------------------------------------------------------------------------
// pre_kernel: pre = Xh @ Wxh^T + bx  (2 CTA/SM)
// ---------------------------------------------------------------------------
__device__ __forceinline__ void pre_issue(uint32_t smbase, int stage,
                                          const __half* __restrict__ Asrc,
                                          const __half* __restrict__ Bsrc,
                                          int kt, int tid) {
    const uint32_t sb = smbase + (uint32_t)(stage * P_STAGE) * 4u;
    #pragma unroll
    for (int j = 0; j < 8; ++j) {
        const int i  = tid + j * 256;
        const int r  = i >> 3;
        const int ch = i & 7;
        const __half* src = (r < 128)
            ? Asrc + (size_t)r * K + kt + ch * 8
            : Bsrc + (size_t)(r - 128) * K + kt + ch * 8;
        cp16(sb + (uint32_t)(r * LDA_P + ch * 4) * 4u, src);
    }
    cp_commit();
}

__global__ __launch_bounds__(256, 2) void pre_kernel(const float* __restrict__ bx) {
    extern __shared__ uint32_t sm_u[];
    const uint32_t smbase = (uint32_t)__cvta_generic_to_shared(sm_u);
    const int tid  = threadIdx.x;
    const int lane = tid & 31;
    const int warp = tid >> 5;
    const int wm = warp >> 2;
    const int wn = warp & 3;
    const int ar = lane >> 2;
    const int aq = lane & 3;

    const __half* Asrc = g_xh  + (size_t)blockIdx.y * 128 * K;
    const __half* Bsrc = g_wxh + (size_t)blockIdx.x * 128 * K;
    float acc[4][4][4] = {};

    pre_issue(smbase, 0, Asrc, Bsrc, 0, tid);
    pre_issue(smbase, 1, Asrc, Bsrc, BKP, tid);

    #pragma unroll 1
    for (int kt = 0; kt < NKT_P; ++kt) {
        if (kt < NKT_P - 2) { cp_wait<1>(); } else { cp_wait<0>(); }
        __syncthreads();
        if (kt + 2 < NKT_P)
            pre_issue(smbase, (kt + 2) % 3, Asrc, Bsrc, (kt + 2) * BKP, tid);

        const uint32_t* buf = sm_u + (kt % 3) * P_STAGE;
        #pragma unroll
        for (int gq = 0; gq < 4; ++gq) {
            const int ac = gq * 8 + aq;
            uint32_t af[4][4], bf[4][2];
            #pragma unroll
            for (int tm = 0; tm < 4; ++tm) {
                const uint32_t* p = buf + (wm * 64 + tm * 16 + ar) * LDA_P + ac;
                af[tm][0] = p[0];
                af[tm][1] = p[8 * LDA_P];
                af[tm][2] = p[4];
                af[tm][3] = p[8 * LDA_P + 4];
            }
            #pragma unroll
            for (int tn = 0; tn < 4; ++tn) {
                const uint32_t* q = buf + (128 + wn * 32 + tn * 8 + ar) * LDA_P + ac;
                bf[tn][0] = q[0];
                bf[tn][1] = q[4];
            }
            #pragma unroll
            for (int tm = 0; tm < 4; ++tm)
                #pragma unroll
                for (int tn = 0; tn < 4; ++tn)
                    mma_f16(&acc[tm][tn][0], af[tm], bf[tn]);
        }
        __syncthreads();
    }

    #pragma unroll
    for (int tm = 0; tm < 4; ++tm)
        #pragma unroll
        for (int tn = 0; tn < 4; ++tn) {
            const int r0 = wm * 64 + tm * 16 + ar;
            const int c0 = wn * 32 + tn * 8 + aq * 2;
            #pragma unroll
            for (int j = 0; j < 4; ++j) {
                const int rr = r0 + (j >> 1) * 8;
                const int cc = c0 + (j & 1);
                const int gm = blockIdx.y * 128 + rr;
                const int gn = blockIdx.x * 128 + cc;
                g_pre[(size_t)gm * NPRE + gn] = acc[tm][tn][j] + __ldg(bx + gn);
            }
        }
}

// ---------------------------------------------------------------------------
// Persistent recurrence kernel (one 256-step segment per launch)
// ---------------------------------------------------------------------------
__device__ __forceinline__ void group_barrier(unsigned* bar, unsigned target) {
    __syncthreads();
    if (threadIdx.x == 0) {
        asm volatile("red.release.gpu.global.add.u32 [%0], %1;\n"
                     :: "l"(bar), "r"(1u) : "memory");
        unsigned v;
        do {
            asm volatile("ld.acquire.gpu.global.u32 %0, [%1];\n"
                         : "=r"(v) : "l"(bar) : "memory");
        } while (v < target);
    }
    __syncthreads();
}

__device__ __forceinline__ void lstm_issueA(uint32_t smbase, int stage,
                                            const __half* __restrict__ src,
                                            int kt, int tid) {
    const uint32_t sb = smbase + (uint32_t)(OFF_AS + stage * ABUF) * 4u;
    #pragma unroll
    for (int q = 0; q < 2; ++q) {
        const int i  = tid + q * 256;
        const int r  = i >> 3;
        const int ch = i & 7;
        cp16(sb + (uint32_t)(r * LDA + ch * 4) * 4u,
             src + (size_t)r * H + kt + ch * 8);
    }
    cp_commit();
}

__global__ __launch_bounds__(256, 1) void lstm_kernel(const float* __restrict__ Wh,
                                                      const float* __restrict__ bh,
                                                      const float* __restrict__ Wum,
                                                      const float* __restrict__ bum,
                                                      float* __restrict__ out,
                                                      int t0, unsigned tgt0) {
    extern __shared__ uint32_t sm_u[];
    const uint32_t smbase = (uint32_t)__cvta_generic_to_shared(sm_u);
    uint32_t* W_s = sm_u + OFF_W;

    const int tid   = threadIdx.x;
    const int lane  = tid & 31;
    const int warp  = tid >> 5;
    const int cta   = blockIdx.x;
    const int grp   = cta >> 6;
    const int jj    = cta & 63;
    const int uBase = jj * UCOLS;
    const int gRow0 = grp * GROWS;
    unsigned* bar   = &g_bars[grp];

    for (int i = tid; i < 80 * 512; i += 256) {
        const int row = i >> 9;
        const int w   = i & 511;
        const float* src = (row < 64)
            ? Wh  + (size_t)((row >> 4) * H + uBase + (row & 15)) * K
            : Wum + (size_t)(uBase + (row - 64)) * K;
        const float2 v = *reinterpret_cast<const float2*>(src + w * 2);
        W_s[row * LDWW + w] = pack_h2(v.x, v.y);
    }
    __syncthreads();

    const int ar = lane >> 2;
    const int aq = lane & 3;
    const int wm = warp >> 1;
    const int wn = warp & 1;
    const int colBase = uBase + wn * 8 + aq * 2;

    float bhreg[4][2];
    #pragma unroll
    for (int g = 0; g < 4; ++g)
        #pragma unroll
        for (int jb = 0; jb < 2; ++jb)
            bhreg[g][jb] = bh[g * H + colBase + jb];
    float bureg[2];
    bureg[0] = bum[colBase];
    bureg[1] = bum[colBase + 1];

    float cst[4];
    #pragma unroll
    for (int jh = 0; jh < 2; ++jh) {
        const int b = wm * 16 + ar + 8 * jh;
        const float2 cv = *reinterpret_cast<const float2*>(
            g_c + (size_t)(gRow0 + b) * H + colBase);
        cst[jh * 2]     = cv.x;
        cst[jh * 2 + 1] = cv.y;
    }

    float ig[4], og[4], fg[4];
    unsigned tgt = tgt0;

    #pragma unroll 1
    for (int t = t0; t < t0 + SEG_STEPS; ++t) {
        const float* pre_t = g_pre + (size_t)t * NB * NPRE;

        // ================= Phase 1: all 4 gates for owned cells ==============
        {
            float2 pre2[4][2];
            #pragma unroll
            for (int g = 0; g < 4; ++g)
                #pragma unroll
                for (int jh = 0; jh < 2; ++jh) {
                    const int b = wm * 16 + ar + 8 * jh;
                    pre2[g][jh] = __ldcg(reinterpret_cast<const float2*>(
                        pre_t + (size_t)(gRow0 + b) * NPRE + g * H + colBase));
                }

            float acc[4][4] = {};
            if (t > 0) {
                const __half* hsrc = g_hh + (size_t)gRow0 * H;
                #pragma unroll
                for (int p = 0; p < 5; ++p)
                    lstm_issueA(smbase, p, hsrc, p * BK, tid);
                #pragma unroll 1
                for (int kt = 0; kt < NKT; ++kt) {
                    if (kt <= NKT - 5)      { cp_wait<4>(); }
                    else if (kt == NKT - 4) { cp_wait<3>(); }
                    else if (kt == NKT - 3) { cp_wait<2>(); }
                    else if (kt == NKT - 2) { cp_wait<1>(); }
                    else                    { cp_wait<0>(); }
                    __syncthreads();
                    if (kt + 5 < NKT)
                        lstm_issueA(smbase, (kt + 5) % NSTG, hsrc, (kt + 5) * BK, tid);

                    const uint32_t* cur = sm_u + OFF_AS + (kt % NSTG) * ABUF;
                    #pragma unroll
                    for (int g4 = 0; g4 < 4; ++g4) {
                        const int ac = g4 * 8 + aq;
                        uint32_t af[4];
                        const uint32_t* p = cur + (wm * 16 + ar) * LDA + ac;
                        af[0] = p[0];
                        af[1] = p[8 * LDA];
                        af[2] = p[4];
                        af[3] = p[8 * LDA + 4];
                        #pragma unroll
                        for (int g = 0; g < 4; ++g) {
                            uint32_t bf[2];
                            const uint32_t* q = W_s + (g * 16 + wn * 8 + ar) * LDWW
                                              + kt * 32 + g4 * 8 + aq;
                            bf[0] = q[0];
                            bf[1] = q[4];
                            mma_f16(&acc[g][0], af, bf);
                        }
                    }
                }
            }

            float zg[4];
            #pragma unroll
            for (int j = 0; j < 4; ++j) {
                const int jb = j & 1, jh = j >> 1;
                ig[j] = fast_sigmoid(acc[0][j] + bhreg[0][jb] + (jb ? pre2[0][jh].y : pre2[0][jh].x));
                og[j] = fast_sigmoid(acc[1][j] + bhreg[1][jb] + (jb ? pre2[1][jh].y : pre2[1][jh].x));
                zg[j] = fast_sigmoid(acc[2][j] + bhreg[2][jb] + (jb ? pre2[2][jh].y : pre2[2][jh].x));
                fg[j] = fast_sigmoid(acc[3][j] + bhreg[3][jb] + (jb ? pre2[3][jh].y : pre2[3][jh].x));
            }
            #pragma unroll
            for (int jh = 0; jh < 2; ++jh) {
                const int b = wm * 16 + ar + 8 * jh;
                const float m0 = zg[jh * 2]     * fast_tanh(cst[jh * 2]);
                const float m1 = zg[jh * 2 + 1] * fast_tanh(cst[jh * 2 + 1]);
                *reinterpret_cast<uint32_t*>(
                    g_mh + (size_t)(gRow0 + b) * H + colBase) = pack_h2(m0, m1);
            }
        }
        group_barrier(bar, tgt); tgt += GCTA;

        // ================= Phase 2: u + state update =========================
        {
            float2 preu[2];
            #pragma unroll
            for (int jh = 0; jh < 2; ++jh) {
                const int b = wm * 16 + ar + 8 * jh;
                preu[jh] = __ldcg(reinterpret_cast<const float2*>(
                    pre_t + (size_t)(gRow0 + b) * NPRE + 4 * H + colBase));
            }

            float acc2[4] = {};
            if (t > 0) {
                const __half* msrc = g_mh + (size_t)gRow0 * H;
                #pragma unroll
                for (int p = 0; p < 5; ++p)
                    lstm_issueA(smbase, p, msrc, p * BK, tid);
                #pragma unroll 1
                for (int kt = 0; kt < NKT; ++kt) {
                    if (kt <= NKT - 5)      { cp_wait<4>(); }
                    else if (kt == NKT - 4) { cp_wait<3>(); }
                    else if (kt == NKT - 3) { cp_wait<2>(); }
                    else if (kt == NKT - 2) { cp_wait<1>(); }
                    else                    { cp_wait<0>(); }
                    __syncthreads();
                    if (kt + 5 < NKT)
                        lstm_issueA(smbase, (kt + 5) % NSTG, msrc, (kt + 5) * BK, tid);

                    const uint32_t* cur = sm_u + OFF_AS + (kt % NSTG) * ABUF;
                    #pragma unroll
                    for (int g4 = 0; g4 < 4; ++g4) {
                        const int ac = g4 * 8 + aq;
                        uint32_t af[4], bf[2];
                        const uint32_t* p = cur + (wm * 16 + ar) * LDA + ac;
                        af[0] = p[0];
                        af[1] = p[8 * LDA];
                        af[2] = p[4];
                        af[3] = p[8 * LDA + 4];
                        const uint32_t* q = W_s + (64 + wn * 8 + ar) * LDWW
                                          + kt * 32 + g4 * 8 + aq;
                        bf[0] = q[0];
                        bf[1] = q[4];
                        mma_f16(acc2, af, bf);
                    }
                }
            }

            #pragma unroll
            for (int jh = 0; jh < 2; ++jh) {
                const int b = wm * 16 + ar + 8 * jh;
                const int j0 = jh * 2;
                const float u0 = fast_tanh(acc2[j0]     + bureg[0] + preu[jh].x);
                const float u1 = fast_tanh(acc2[j0 + 1] + bureg[1] + preu[jh].y);
                const float cn0 = ig[j0]     * u0 + fg[j0]     * cst[j0];
                const float cn1 = ig[j0 + 1] * u1 + fg[j0 + 1] * cst[j0 + 1];
                cst[j0]     = cn0;
                cst[j0 + 1] = cn1;
                const float hv0 = og[j0]     * fast_tanh(cn0);
                const float hv1 = og[j0 + 1] * fast_tanh(cn1);
                *reinterpret_cast<float2*>(
                    out + ((size_t)t * NB + gRow0 + b) * H + colBase) =
                    make_float2(hv0, hv1);
                *reinterpret_cast<uint32_t*>(
                    g_hh + (size_t)(gRow0 + b) * H + colBase) = pack_h2(hv0, hv1);
                if (t == SEQ - 1) {
                    float* hn = out + ((size_t)SEQ * NB + gRow0 + b) * H + colBase;
                    float* cn = hn + (size_t)NB * H;
                    *reinterpret_cast<float2*>(hn) = make_float2(hv0, hv1);
                    *reinterpret_cast<float2*>(cn) = make_float2(cn0, cn1);
                }
            }
        }
        group_barrier(bar, tgt); tgt += GCTA;
    }

    // persist c for next segment
    #pragma unroll
    for (int jh = 0; jh < 2; ++jh) {
        const int b = wm * 16 + ar + 8 * jh;
        *reinterpret_cast<float2*>(g_c + (size_t)(gRow0 + b) * H + colBase) =
            make_float2(cst[jh * 2], cst[jh * 2 + 1]);
    }
}

extern "C" void kernel_launch(void* const* d_in, const int* in_sizes, int n_in,
                              void* d_out, int out_size) {
    (void)in_sizes; (void)n_in; (void)out_size;
    const float* X   = (const float*)d_in[0];
    const float* Wx  = (const float*)d_in[1];
    const float* bx  = (const float*)d_in[2];
    const float* Wh  = (const float*)d_in[3];
    const float* bh  = (const float*)d_in[4];
    const float* Wum = (const float*)d_in[5];
    const float* bum = (const float*)d_in[6];
    float* out = (float*)d_out;

    static_assert(SMEM_WORDS * 4 == 220416, "lstm smem layout");
    cudaFuncSetAttribute(lstm_kernel, cudaFuncAttributeMaxDynamicSharedMemorySize,
                         SMEM_WORDS * 4);
    cudaFuncSetAttribute(pre_kernel, cudaFuncAttributeMaxDynamicSharedMemorySize,
                         P_SMEM * 4);

    const size_t total4 = X4 + W4;
    round_kernel<<<(unsigned)((total4 + 255) / 256), 256>>>(
        (const float4*)X, (const float4*)Wx);
    pre_kernel<<<dim3(NPRE / 128, (SEQ * NB) / 128), 256, P_SMEM * 4>>>(bx);
    for (int s = 0; s < SEGS; ++s) {
        lstm_kernel<<<128, 256, SMEM_WORDS * 4>>>(
            Wh, bh, Wum, bum, out,
            s * SEG_STEPS, (unsigned)(s * SEG_STEPS * 2 * GCTA + GCTA));
    }
}

// round 17
// speedup vs baseline: 1.3963x; 1.0075x over previous
#include <cuda_runtime.h>
#include <cuda_fp16.h>
#include <math.h>
#include <stdint.h>

// ---------------------------------------------------------------------------
// FPLSTM: S=512, B=128, I=H=1024.
//   pre = X @ Wx^T + bx            (SIMT fp16 mma, cp.async 3-stage, 2 CTA/SM)
//   recurrence: persistent CTAs, 2 independent groups of 64, 2 segment
//   launches of 256 steps; each warp owns (16 rows x 8 cols), computes all
//   4 gates AND u for those cells -> i/o/f/c in registers, no smem state.
//   6-stage / 5-ahead cp.async pipeline on the streamed h/m tiles.
//   R17: g_pre stored in fp16 (halves pre-store + epilogue-read traffic).
// ---------------------------------------------------------------------------

namespace {
constexpr int SEQ  = 512;
constexpr int NB   = 128;
constexpr int K    = 1024;
constexpr int H    = 1024;
constexpr int NPRE = 5 * H;

constexpr int GCTA  = 64;
constexpr int GROWS = 64;
constexpr int UCOLS = 16;
constexpr int LDWW  = K / 2 + 4;     // 516 words
constexpr int BK    = 64;
constexpr int NKT   = K / BK;        // 16
constexpr int LDA   = 36;
constexpr int ABUF  = GROWS * LDA;   // 2304 words (9216 B) per stage
constexpr int NSTG  = 6;

constexpr int OFF_W   = 0;                       // 80 rows x LDWW
constexpr int OFF_AS  = 80 * LDWW;               // 41280
constexpr int SMEM_WORDS = OFF_AS + NSTG * ABUF; // 55104 -> 220416 B

constexpr int SEGS      = 2;
constexpr int SEG_STEPS = SEQ / SEGS;            // 256

constexpr int LDA_P  = 36;
constexpr int P_STAGE = 256 * LDA_P;
constexpr int P_SMEM  = 3 * P_STAGE;             // 110592 B
constexpr int BKP    = 64;
constexpr int NKT_P  = 16;
constexpr size_t X4 = (size_t)SEQ * NB * K / 4;
constexpr size_t W4 = (size_t)NPRE * K / 4;
}

__device__ __align__(16) __half g_pre[(size_t)SEQ * NB * NPRE];   // fp16 now
__device__ __align__(16) __half g_xh[(size_t)SEQ * NB * K];
__device__ __align__(16) __half g_wxh[(size_t)NPRE * K];
__device__ __align__(16) __half g_hh[NB * H];
__device__ __align__(16) __half g_mh[NB * H];
__device__ __align__(16) float  g_c[NB * H];
__device__ unsigned g_bars[2];

__device__ __forceinline__ uint32_t pack_h2(float x, float y) {
    __half2 h = __floats2half2_rn(x, y);
    return *reinterpret_cast<uint32_t*>(&h);
}
__device__ __forceinline__ float2 unpack_h2(uint32_t u) {
    const __half2 h = *reinterpret_cast<const __half2*>(&u);
    return __half22float2(h);
}
__device__ __forceinline__ float fast_sigmoid(float x) {
    return __fdividef(1.0f, 1.0f + __expf(-x));
}
__device__ __forceinline__ float fast_tanh(float x) {
    return 1.0f - __fdividef(2.0f, __expf(2.0f * x) + 1.0f);
}
__device__ __forceinline__ void cp16(uint32_t saddr, const void* g) {
    asm volatile("cp.async.cg.shared.global [%0], [%1], 16;\n" :: "r"(saddr), "l"(g));
}
__device__ __forceinline__ void cp_commit() { asm volatile("cp.async.commit_group;\n"); }
template <int N> __device__ __forceinline__ void cp_wait() {
    asm volatile("cp.async.wait_group %0;\n" :: "n"(N));
}
__device__ __forceinline__ void mma_f16(float* c, const uint32_t* a, const uint32_t* b) {
    asm volatile(
        "mma.sync.aligned.m16n8k16.row.col.f32.f16.f16.f32 "
        "{%0,%1,%2,%3}, {%4,%5,%6,%7}, {%8,%9}, {%0,%1,%2,%3};\n"
        : "+f"(c[0]), "+f"(c[1]), "+f"(c[2]), "+f"(c[3])
        : "r"(a[0]), "r"(a[1]), "r"(a[2]), "r"(a[3]), "r"(b[0]), "r"(b[1]));
}

// ---------------------------------------------------------------------------
// round_kernel: fp16-convert X and Wx; zero c state; reset barriers
// ---------------------------------------------------------------------------
__global__ __launch_bounds__(256) void round_kernel(const float4* __restrict__ X,
                                                    const float4* __restrict__ Wx) {
    const size_t i = (size_t)blockIdx.x * 256 + threadIdx.x;
    if (i < 2) g_bars[i] = 0u;
    if (i < (size_t)(NB * H / 4))
        reinterpret_cast<float4*>(g_c)[i] = make_float4(0.f, 0.f, 0.f, 0.f);
    if (i < X4) {
        const float4 v = X[i];
        reinterpret_cast<uint2*>(g_xh)[i] = make_uint2(pack_h2(v.x, v.y), pack_h2(v.z, v.w));
    } else if (i < X4 + W4) {
        const size_t j = i - X4;
        const float4 v = Wx[j];
        reinterpret_cast<uint2*>(g_wxh)[j] = make_uint2(pack_h2(v.x, v.y), pack_h2(v.z, v.w));
    }
}

// ---------------------------------------------------------------------------
// pre_kernel: pre = Xh @ Wxh^T + bx  (2 CTA/SM; fp16 output)
// ---------------------------------------------------------------------------
__device__ __forceinline__ void pre_issue(uint32_t smbase, int stage,
                                          const __half* __restrict__ Asrc,
                                          const __half* __restrict__ Bsrc,
                                          int kt, int tid) {
    const uint32_t sb = smbase + (uint32_t)(stage * P_STAGE) * 4u;
    #pragma unroll
    for (int j = 0; j < 8; ++j) {
        const int i  = tid + j * 256;
        const int r  = i >> 3;
        const int ch = i & 7;
        const __half* src = (r < 128)
            ? Asrc + (size_t)r * K + kt + ch * 8
            : Bsrc + (size_t)(r - 128) * K + kt + ch * 8;
        cp16(sb + (uint32_t)(r * LDA_P + ch * 4) * 4u, src);
    }
    cp_commit();
}

__global__ __launch_bounds__(256, 2) void pre_kernel(const float* __restrict__ bx) {
    extern __shared__ uint32_t sm_u[];
    const uint32_t smbase = (uint32_t)__cvta_generic_to_shared(sm_u);
    const int tid  = threadIdx.x;
    const int lane = tid & 31;
    const int warp = tid >> 5;
    const int wm = warp >> 2;
    const int wn = warp & 3;
    const int ar = lane >> 2;
    const int aq = lane & 3;

    const __half* Asrc = g_xh  + (size_t)blockIdx.y * 128 * K;
    const __half* Bsrc = g_wxh + (size_t)blockIdx.x * 128 * K;
    float acc[4][4][4] = {};

    pre_issue(smbase, 0, Asrc, Bsrc, 0, tid);
    pre_issue(smbase, 1, Asrc, Bsrc, BKP, tid);

    #pragma unroll 1
    for (int kt = 0; kt < NKT_P; ++kt) {
        if (kt < NKT_P - 2) { cp_wait<1>(); } else { cp_wait<0>(); }
        __syncthreads();
        if (kt + 2 < NKT_P)
            pre_issue(smbase, (kt + 2) % 3, Asrc, Bsrc, (kt + 2) * BKP, tid);

        const uint32_t* buf = sm_u + (kt % 3) * P_STAGE;
        #pragma unroll
        for (int gq = 0; gq < 4; ++gq) {
            const int ac = gq * 8 + aq;
            uint32_t af[4][4], bf[4][2];
            #pragma unroll
            for (int tm = 0; tm < 4; ++tm) {
                const uint32_t* p = buf + (wm * 64 + tm * 16 + ar) * LDA_P + ac;
                af[tm][0] = p[0];
                af[tm][1] = p[8 * LDA_P];
                af[tm][2] = p[4];
                af[tm][3] = p[8 * LDA_P + 4];
            }
            #pragma unroll
            for (int tn = 0; tn < 4; ++tn) {
                const uint32_t* q = buf + (128 + wn * 32 + tn * 8 + ar) * LDA_P + ac;
                bf[tn][0] = q[0];
                bf[tn][1] = q[4];
            }
            #pragma unroll
            for (int tm = 0; tm < 4; ++tm)
                #pragma unroll
                for (int tn = 0; tn < 4; ++tn)
                    mma_f16(&acc[tm][tn][0], af[tm], bf[tn]);
        }
        __syncthreads();
    }

    // epilogue: fp16-pack pairs of adjacent columns (j-pairs (0,1),(2,3))
    #pragma unroll
    for (int tm = 0; tm < 4; ++tm)
        #pragma unroll
        for (int tn = 0; tn < 4; ++tn) {
            const int r0 = wm * 64 + tm * 16 + ar;
            const int c0 = wn * 32 + tn * 8 + aq * 2;
            #pragma unroll
            for (int jh = 0; jh < 2; ++jh) {
                const int rr = r0 + jh * 8;
                const int gm = blockIdx.y * 128 + rr;
                const int gn = blockIdx.x * 128 + c0;
                const float b0 = __ldg(bx + gn);
                const float b1 = __ldg(bx + gn + 1);
                *reinterpret_cast<uint32_t*>(g_pre + (size_t)gm * NPRE + gn) =
                    pack_h2(acc[tm][tn][jh * 2] + b0, acc[tm][tn][jh * 2 + 1] + b1);
            }
        }
}

// ---------------------------------------------------------------------------
// Persistent recurrence kernel (one 256-step segment per launch)
// ---------------------------------------------------------------------------
__device__ __forceinline__ void group_barrier(unsigned* bar, unsigned target) {
    __syncthreads();
    if (threadIdx.x == 0) {
        asm volatile("red.release.gpu.global.add.u32 [%0], %1;\n"
                     :: "l"(bar), "r"(1u) : "memory");
        unsigned v;
        do {
            asm volatile("ld.acquire.gpu.global.u32 %0, [%1];\n"
                         : "=r"(v) : "l"(bar) : "memory");
        } while (v < target);
    }
    __syncthreads();
}

__device__ __forceinline__ void lstm_issueA(uint32_t smbase, int stage,
                                            const __half* __restrict__ src,
                                            int kt, int tid) {
    const uint32_t sb = smbase + (uint32_t)(OFF_AS + stage * ABUF) * 4u;
    #pragma unroll
    for (int q = 0; q < 2; ++q) {
        const int i  = tid + q * 256;
        const int r  = i >> 3;
        const int ch = i & 7;
        cp16(sb + (uint32_t)(r * LDA + ch * 4) * 4u,
             src + (size_t)r * H + kt + ch * 8);
    }
    cp_commit();
}

__global__ __launch_bounds__(256, 1) void lstm_kernel(const float* __restrict__ Wh,
                                                      const float* __restrict__ bh,
                                                      const float* __restrict__ Wum,
                                                      const float* __restrict__ bum,
                                                      float* __restrict__ out,
                                                      int t0, unsigned tgt0) {
    extern __shared__ uint32_t sm_u[];
    const uint32_t smbase = (uint32_t)__cvta_generic_to_shared(sm_u);
    uint32_t* W_s = sm_u + OFF_W;

    const int tid   = threadIdx.x;
    const int lane  = tid & 31;
    const int warp  = tid >> 5;
    const int cta   = blockIdx.x;
    const int grp   = cta >> 6;
    const int jj    = cta & 63;
    const int uBase = jj * UCOLS;
    const int gRow0 = grp * GROWS;
    unsigned* bar   = &g_bars[grp];

    for (int i = tid; i < 80 * 512; i += 256) {
        const int row = i >> 9;
        const int w   = i & 511;
        const float* src = (row < 64)
            ? Wh  + (size_t)((row >> 4) * H + uBase + (row & 15)) * K
            : Wum + (size_t)(uBase + (row - 64)) * K;
        const float2 v = *reinterpret_cast<const float2*>(src + w * 2);
        W_s[row * LDWW + w] = pack_h2(v.x, v.y);
    }
    __syncthreads();

    const int ar = lane >> 2;
    const int aq = lane & 3;
    const int wm = warp >> 1;
    const int wn = warp & 1;
    const int colBase = uBase + wn * 8 + aq * 2;

    float bhreg[4][2];
    #pragma unroll
    for (int g = 0; g < 4; ++g)
        #pragma unroll
        for (int jb = 0; jb < 2; ++jb)
            bhreg[g][jb] = bh[g * H + colBase + jb];
    float bureg[2];
    bureg[0] = bum[colBase];
    bureg[1] = bum[colBase + 1];

    float cst[4];
    #pragma unroll
    for (int jh = 0; jh < 2; ++jh) {
        const int b = wm * 16 + ar + 8 * jh;
        const float2 cv = *reinterpret_cast<const float2*>(
            g_c + (size_t)(gRow0 + b) * H + colBase);
        cst[jh * 2]     = cv.x;
        cst[jh * 2 + 1] = cv.y;
    }

    float ig[4], og[4], fg[4];
    unsigned tgt = tgt0;

    #pragma unroll 1
    for (int t = t0; t < t0 + SEG_STEPS; ++t) {
        const __half* pre_t = g_pre + (size_t)t * NB * NPRE;

        // ================= Phase 1: all 4 gates for owned cells ==============
        {
            float2 pre2[4][2];
            #pragma unroll
            for (int g = 0; g < 4; ++g)
                #pragma unroll
                for (int jh = 0; jh < 2; ++jh) {
                    const int b = wm * 16 + ar + 8 * jh;
                    const uint32_t u = __ldcg(reinterpret_cast<const uint32_t*>(
                        pre_t + (size_t)(gRow0 + b) * NPRE + g * H + colBase));
                    pre2[g][jh] = unpack_h2(u);
                }

            float acc[4][4] = {};
            if (t > 0) {
                const __half* hsrc = g_hh + (size_t)gRow0 * H;
                #pragma unroll
                for (int p = 0; p < 5; ++p)
                    lstm_issueA(smbase, p, hsrc, p * BK, tid);
                #pragma unroll 1
                for (int kt = 0; kt < NKT; ++kt) {
                    if (kt <= NKT - 5)      { cp_wait<4>(); }
                    else if (kt == NKT - 4) { cp_wait<3>(); }
                    else if (kt == NKT - 3) { cp_wait<2>(); }
                    else if (kt == NKT - 2) { cp_wait<1>(); }
                    else                    { cp_wait<0>(); }
                    __syncthreads();
                    if (kt + 5 < NKT)
                        lstm_issueA(smbase, (kt + 5) % NSTG, hsrc, (kt + 5) * BK, tid);

                    const uint32_t* cur = sm_u + OFF_AS + (kt % NSTG) * ABUF;
                    #pragma unroll
                    for (int g4 = 0; g4 < 4; ++g4) {
                        const int ac = g4 * 8 + aq;
                        uint32_t af[4];
                        const uint32_t* p = cur + (wm * 16 + ar) * LDA + ac;
                        af[0] = p[0];
                        af[1] = p[8 * LDA];
                        af[2] = p[4];
                        af[3] = p[8 * LDA + 4];
                        #pragma unroll
                        for (int g = 0; g < 4; ++g) {
                            uint32_t bf[2];
                            const uint32_t* q = W_s + (g * 16 + wn * 8 + ar) * LDWW
                                              + kt * 32 + g4 * 8 + aq;
                            bf[0] = q[0];
                            bf[1] = q[4];
                            mma_f16(&acc[g][0], af, bf);
                        }
                    }
                }
            }

            float zg[4];
            #pragma unroll
            for (int j = 0; j < 4; ++j) {
                const int jb = j & 1, jh = j >> 1;
                ig[j] = fast_sigmoid(acc[0][j] + bhreg[0][jb] + (jb ? pre2[0][jh].y : pre2[0][jh].x));
                og[j] = fast_sigmoid(acc[1][j] + bhreg[1][jb] + (jb ? pre2[1][jh].y : pre2[1][jh].x));
                zg[j] = fast_sigmoid(acc[2][j] + bhreg[2][jb] + (jb ? pre2[2][jh].y : pre2[2][jh].x));
                fg[j] = fast_sigmoid(acc[3][j] + bhreg[3][jb] + (jb ? pre2[3][jh].y : pre2[3][jh].x));
            }
            #pragma unroll
            for (int jh = 0; jh < 2; ++jh) {
                const int b = wm * 16 + ar + 8 * jh;
                const float m0 = zg[jh * 2]     * fast_tanh(cst[jh * 2]);
                const float m1 = zg[jh * 2 + 1] * fast_tanh(cst[jh * 2 + 1]);
                *reinterpret_cast<uint32_t*>(
                    g_mh + (size_t)(gRow0 + b) * H + colBase) = pack_h2(m0, m1);
            }
        }
        group_barrier(bar, tgt); tgt += GCTA;

        // ================= Phase 2: u + state update =========================
        {
            float2 preu[2];
            #pragma unroll
            for (int jh = 0; jh < 2; ++jh) {
                const int b = wm * 16 + ar + 8 * jh;
                const uint32_t u = __ldcg(reinterpret_cast<const uint32_t*>(
                    pre_t + (size_t)(gRow0 + b) * NPRE + 4 * H + colBase));
                preu[jh] = unpack_h2(u);
            }

            float acc2[4] = {};
            if (t > 0) {
                const __half* msrc = g_mh + (size_t)gRow0 * H;
                #pragma unroll
                for (int p = 0; p < 5; ++p)
                    lstm_issueA(smbase, p, msrc, p * BK, tid);
                #pragma unroll 1
                for (int kt = 0; kt < NKT; ++kt) {
                    if (kt <= NKT - 5)      { cp_wait<4>(); }
                    else if (kt == NKT - 4) { cp_wait<3>(); }
                    else if (kt == NKT - 3) { cp_wait<2>(); }
                    else if (kt == NKT - 2) { cp_wait<1>(); }
                    else                    { cp_wait<0>(); }
                    __syncthreads();
                    if (kt + 5 < NKT)
                        lstm_issueA(smbase, (kt + 5) % NSTG, msrc, (kt + 5) * BK, tid);

                    const uint32_t* cur = sm_u + OFF_AS + (kt % NSTG) * ABUF;
                    #pragma unroll
                    for (int g4 = 0; g4 < 4; ++g4) {
                        const int ac = g4 * 8 + aq;
                        uint32_t af[4], bf[2];
                        const uint32_t* p = cur + (wm * 16 + ar) * LDA + ac;
                        af[0] = p[0];
                        af[1] = p[8 * LDA];
                        af[2] = p[4];
                        af[3] = p[8 * LDA + 4];
                        const uint32_t* q = W_s + (64 + wn * 8 + ar) * LDWW
                                          + kt * 32 + g4 * 8 + aq;
                        bf[0] = q[0];
                        bf[1] = q[4];
                        mma_f16(acc2, af, bf);
                    }
                }
            }

            #pragma unroll
            for (int jh = 0; jh < 2; ++jh) {
                const int b = wm * 16 + ar + 8 * jh;
                const int j0 = jh * 2;
                const float u0 = fast_tanh(acc2[j0]     + bureg[0] + preu[jh].x);
                const float u1 = fast_tanh(acc2[j0 + 1] + bureg[1] + preu[jh].y);
                const float cn0 = ig[j0]     * u0 + fg[j0]     * cst[j0];
                const float cn1 = ig[j0 + 1] * u1 + fg[j0 + 1] * cst[j0 + 1];
                cst[j0]     = cn0;
                cst[j0 + 1] = cn1;
                const float hv0 = og[j0]     * fast_tanh(cn0);
                const float hv1 = og[j0 + 1] * fast_tanh(cn1);
                *reinterpret_cast<float2*>(
                    out + ((size_t)t * NB + gRow0 + b) * H + colBase) =
                    make_float2(hv0, hv1);
                *reinterpret_cast<uint32_t*>(
                    g_hh + (size_t)(gRow0 + b) * H + colBase) = pack_h2(hv0, hv1);
                if (t == SEQ - 1) {
                    float* hn = out + ((size_t)SEQ * NB + gRow0 + b) * H + colBase;
                    float* cn = hn + (size_t)NB * H;
                    *reinterpret_cast<float2*>(hn) = make_float2(hv0, hv1);
                    *reinterpret_cast<float2*>(cn) = make_float2(cn0, cn1);
                }
            }
        }
        group_barrier(bar, tgt); tgt += GCTA;
    }

    // persist c for next segment
    #pragma unroll
    for (int jh = 0; jh < 2; ++jh) {
        const int b = wm * 16 + ar + 8 * jh;
        *reinterpret_cast<float2*>(g_c + (size_t)(gRow0 + b) * H + colBase) =
            make_float2(cst[jh * 2], cst[jh * 2 + 1]);
    }
}

extern "C" void kernel_launch(void* const* d_in, const int* in_sizes, int n_in,
                              void* d_out, int out_size) {
    (void)in_sizes; (void)n_in; (void)out_size;
    const float* X   = (const float*)d_in[0];
    const float* Wx  = (const float*)d_in[1];
    const float* bx  = (const float*)d_in[2];
    const float* Wh  = (const float*)d_in[3];
    const float* bh  = (const float*)d_in[4];
    const float* Wum = (const float*)d_in[5];
    const float* bum = (const float*)d_in[6];
    float* out = (float*)d_out;

    static_assert(SMEM_WORDS * 4 == 220416, "lstm smem layout");
    cudaFuncSetAttribute(lstm_kernel, cudaFuncAttributeMaxDynamicSharedMemorySize,
                         SMEM_WORDS * 4);
    cudaFuncSetAttribute(pre_kernel, cudaFuncAttributeMaxDynamicSharedMemorySize,
                         P_SMEM * 4);

    const size_t total4 = X4 + W4;
    round_kernel<<<(unsigned)((total4 + 255) / 256), 256>>>(
        (const float4*)X, (const float4*)Wx);
    pre_kernel<<<dim3(NPRE / 128, (SEQ * NB) / 128), 256, P_SMEM * 4>>>(bx);
    for (int s = 0; s < SEGS; ++s) {
        lstm_kernel<<<128, 256, SMEM_WORDS * 4>>>(
            Wh, bh, Wum, bum, out,
            s * SEG_STEPS, (unsigned)(s * SEG_STEPS * 2 * GCTA + GCTA));
    }
}